// round 15
// baseline (speedup 1.0000x reference)
#include <cuda_runtime.h>

#define NGT   8000
#define NSAMP 4000
#define TILE  128
#define TILE2 256             // inner tile (points) per sync
#define MAXV  10242
#define MAXM  (MAXV + NSAMP)
#define SEGS  16              // d2 segment count (fixed; rescan/combine depend on it)
#define NPT   4
#define PTSPB (TILE * NPT)    // 512 outer points per block
typedef unsigned long long ull;

static __device__ double g_loss;        // zero-init; final writer re-zeroes each run
static __device__ unsigned g_tick;      // same
static __device__ unsigned g_done;      // rescan completion counter, same
static __device__ int    g_imin[3][MAXV];
static __device__ unsigned g_best1[3][NGT];          // encoded max-score, gt->pred
static __device__ float    g_d2seg[3][SEGS][MAXM];   // per-segment max score, pred->gt
static __device__ float4   g_gtp[NGT];               // gt packed (x,y,z,-0.5|q|^2)
static __device__ float4   g_pp[3][MAXM];            // pred+samples packed

#define V0 642
#define V1 2562
#define V2 10242
#define VSUM 13446
#define ESUM 40338

struct Params {
  const float* gt;  const float* gtn;
  const float* pred[3]; const float* bef[3];
  const int*   edges[3]; const int* faces[3]; const int* lap[3];
  float* out;
};

__device__ __forceinline__ int vb_of(int b) { return b == 0 ? V0 : (b == 1 ? V1 : V2); }

__device__ __forceinline__ unsigned enc_f(float f) {
  unsigned u = __float_as_uint(f);
  return (u & 0x80000000u) ? ~u : (u | 0x80000000u);
}
__device__ __forceinline__ float dec_f(unsigned u) {
  unsigned b = (u & 0x80000000u) ? (u ^ 0x80000000u) : ~u;
  return __uint_as_float(b);
}

// ---- packed f32x2 helpers ----
__device__ __forceinline__ ull ffma2(ull a, ull b, ull c) {
  ull d;
  asm("fma.rn.f32x2 %0, %1, %2, %3;" : "=l"(d) : "l"(a), "l"(b), "l"(c));
  return d;
}
__device__ __forceinline__ ull dup2(float v) {
  ull r; unsigned u = __float_as_uint(v);
  asm("mov.b64 %0, {%1, %1};" : "=l"(r) : "r"(u));
  return r;
}
__device__ __forceinline__ void unpk(ull v, float& lo, float& hi) {
  unsigned l, h;
  asm("mov.b64 {%0, %1}, %2;" : "=r"(l), "=r"(h) : "l"(v));
  lo = __uint_as_float(l); hi = __uint_as_float(h);
}
// 3-input max (PTX ISA 8.0+, sm_90+): SASS FMNMX3
__device__ __forceinline__ float fmax3(float a, float b, float c) {
  float d;
  asm("max.f32 %0, %1, %2, %3;" : "=f"(d) : "f"(a), "f"(b), "f"(c));
  return d;
}

// pinned-rounding score pieces (bit-identical everywhere)
__device__ __forceinline__ float wneg_of(float qx, float qy, float qz) {
  return -0.5f * __fmaf_rn(qx, qx, __fmaf_rn(qy, qy, __fmul_rn(qz, qz)));
}
__device__ __forceinline__ float score_of(float x, float y, float z,
                                          float qx, float qy, float qz, float w) {
  return __fmaf_rn(x, qx, __fmaf_rn(y, qy, __fmaf_rn(z, qz, w)));
}

// ---------------- threefry2x32 (exact JAX block) ----------------
__device__ __forceinline__ void tf(unsigned k0, unsigned k1,
                                   unsigned x0, unsigned x1,
                                   unsigned& o0, unsigned& o1) {
  unsigned ks2 = k0 ^ k1 ^ 0x1BD11BDAu;
  x0 += k0; x1 += k1;
#define R_(r) { x0 += x1; x1 = (x1 << (r)) | (x1 >> (32 - (r))); x1 ^= x0; }
  R_(13) R_(15) R_(26) R_(6)  x0 += k1;  x1 += ks2 + 1u;
  R_(17) R_(29) R_(16) R_(24) x0 += ks2; x1 += k0  + 2u;
  R_(13) R_(15) R_(26) R_(6)  x0 += k0;  x1 += k1  + 3u;
  R_(17) R_(29) R_(16) R_(24) x0 += k1;  x1 += ks2 + 4u;
  R_(13) R_(15) R_(26) R_(6)  x0 += ks2; x1 += k0  + 5u;
#undef R_
  o0 = x0; o1 = x1;
}

__device__ __forceinline__ void block_add(double v) {
  #pragma unroll
  for (int o = 16; o; o >>= 1) v += __shfl_down_sync(0xffffffffu, v, o);
  __shared__ double ws[4];
  int lane = threadIdx.x & 31, w = threadIdx.x >> 5;
  if (lane == 0) ws[w] = v;
  __syncthreads();
  if (w == 0) {
    double t = (lane < 4) ? ws[lane] : 0.0;
    t += __shfl_down_sync(0xffffffffu, t, 2);
    t += __shfl_down_sync(0xffffffffu, t, 1);
    if (lane == 0) atomicAdd(&g_loss, t);
  }
}

__device__ __forceinline__ void bv_of(int f, int& b, int& v) {
  if (f < V0)            { b = 0; v = f; }
  else if (f < V0 + V1)  { b = 1; v = f - V0; }
  else                   { b = 2; v = f - (V0 + V1); }
}

// ---------------- prep: block-aligned roles + laplacian loss ----------------
// [0,94) sample; [94,200) pack pred; [200,263) pack gt; [263,451) reset g_best1;
// [451,557) laplacian+move (calls block_add; roles are block-granular => uniform barrier)
#define PREP_BLKS 557
__global__ void k_prep(Params P) {
  int blk = blockIdx.x;
  int tid = threadIdx.x;

  if (blk < 94) {                        // ---- sampling (exact JAX PRNG)
    int i = blk * TILE + tid;
    if (i >= 12000) return;
    int b = i / NSAMP;
    int s_i = i - b * NSAMP;
    int Vb = vb_of(b);
    unsigned span = 2u * (unsigned)Vb;
    unsigned kb0, kb1; tf(0u, 42u, 0u, (unsigned)b, kb0, kb1);
    unsigned kf0, kf1, ku0, ku1, k10, k11, k20, k21, t0, t1, hi, lo, u0b, u1b;
    tf(kb0, kb1, 0u, 0u, kf0, kf1);
    tf(kb0, kb1, 0u, 1u, ku0, ku1);
    tf(kf0, kf1, 0u, 0u, k10, k11);
    tf(kf0, kf1, 0u, 1u, k20, k21);
    tf(k10, k11, 0u, (unsigned)s_i, t0, t1);            hi  = t0 ^ t1;
    tf(k20, k21, 0u, (unsigned)s_i, t0, t1);            lo  = t0 ^ t1;
    tf(ku0, ku1, 0u, (unsigned)(2 * s_i),     t0, t1);  u0b = t0 ^ t1;
    tf(ku0, ku1, 0u, (unsigned)(2 * s_i + 1), t0, t1);  u1b = t0 ^ t1;
    unsigned m = 65536u % span; m = (m * m) % span;
    int fidx = (int)(((hi % span) * m + (lo % span)) % span);
    float u0 = __uint_as_float((u0b >> 9) | 0x3F800000u) - 1.0f;
    float u1 = __uint_as_float((u1b >> 9) | 0x3F800000u) - 1.0f;
    float r1 = sqrtf(u0);
    float w0 = 1.0f - r1, w1 = r1 * (1.0f - u1), w2 = r1 * u1;
    const int* f = P.faces[b] + 3 * fidx;
    const float* pr = P.pred[b];
    int v0 = f[0], v1 = f[1], v2 = f[2];
    float sx = w0 * pr[3 * v0]     + w1 * pr[3 * v1]     + w2 * pr[3 * v2];
    float sy = w0 * pr[3 * v0 + 1] + w1 * pr[3 * v1 + 1] + w2 * pr[3 * v2 + 1];
    float sz = w0 * pr[3 * v0 + 2] + w1 * pr[3 * v1 + 2] + w2 * pr[3 * v2 + 2];
    g_pp[b][Vb + s_i] = make_float4(sx, sy, sz, wneg_of(sx, sy, sz));
    return;
  } else if (blk < 200) {                // ---- pack pred vertices
    int i = (blk - 94) * TILE + tid;
    if (i < VSUM) {
      int b, v; bv_of(i, b, v);
      const float* s = P.pred[b] + 3 * v;
      float x = s[0], y = s[1], z = s[2];
      g_pp[b][v] = make_float4(x, y, z, wneg_of(x, y, z));
    }
    return;
  } else if (blk < 263) {                // ---- pack gt
    int g = (blk - 200) * TILE + tid;
    if (g < NGT) {
      const float* s = P.gt + 3 * g;
      float x = s[0], y = s[1], z = s[2];
      g_gtp[g] = make_float4(x, y, z, wneg_of(x, y, z));
    }
    return;
  } else if (blk < 451) {                // ---- reset g_best1
    int j = (blk - 263) * TILE + tid;
    if (j < 3 * NGT) (&g_best1[0][0])[j] = 0u;
    return;
  }

  // ---- laplacian + move loss (blocks [451,557); ALL threads reach block_add)
  double acc = 0.0;
  {
    int idx = (blk - 451) * TILE + tid;
    if (idx < VSUM) {
      int b, i; bv_of(idx, b, i);
      int Vb = vb_of(b);
      float lapc = (b == 0) ? 0.2f : 1.0f;
      const int* row = P.lap[b] + 10 * i;
      float cnt = (float)row[9];
      const float* pr = P.pred[b];
      const float* bf = P.bef[b];
      float spx = 0, spy = 0, spz = 0, sbx = 0, sby = 0, sbz = 0;
      #pragma unroll
      for (int k = 0; k < 8; k++) {
        int n = row[k];
        if (n >= 0) {
          spx += pr[3 * n]; spy += pr[3 * n + 1]; spz += pr[3 * n + 2];
          sbx += bf[3 * n]; sby += bf[3 * n + 1]; sbz += bf[3 * n + 2];
        }
      }
      float lbx = bf[3 * i]     - sbx / cnt;
      float lby = bf[3 * i + 1] - sby / cnt;
      float lbz = bf[3 * i + 2] - sbz / cnt;
      float lpx = pr[3 * i]     - spx / cnt;
      float lpy = pr[3 * i + 1] - spy / cnt;
      float lpz = pr[3 * i + 2] - spz / cnt;
      float d0 = lbx - lpx, d1 = lby - lpy, d2 = lbz - lpz;
      float lapsq = d0 * d0 + d1 * d1 + d2 * d2;
      float m0 = bf[3 * i] - pr[3 * i];
      float m1 = bf[3 * i + 1] - pr[3 * i + 1];
      float m2 = bf[3 * i + 2] - pr[3 * i + 2];
      float movesq = m0 * m0 + m1 * m1 + m2 * m2;
      acc = (1500.0 * (double)lapc / Vb) * (double)lapsq;
      if (b > 0) acc += (50.0 * (double)lapc / Vb) * (double)movesq;
    }
  }
  block_add(acc);
}

// ---------------- fused chamfer: double-buffered 256-pt tiles + FMNMX3 ----------------
// d1 (inner = Mb): b0 10 segs (len 465), b1 13 (505), b2 28 (509); 16 xb -> 816 blocks
// d2 (inner = NGT): SEGS=16 (len 500); xb 10/13/28 -> 816.  Total 1632.
__global__ void __launch_bounds__(TILE, 8) k_cham(Params P) {
  int s = blockIdx.x;
  int b, xb, seg, segLen; bool d2;
  if (s < 816) {
    d2 = false;
    if (s < 160)      { b = 0; segLen = 465; }
    else if (s < 368) { b = 1; s -= 160; segLen = 505; }
    else              { b = 2; s -= 368; segLen = 509; }
    xb = s & 15; seg = s >> 4;
  } else {
    d2 = true; s -= 816; segLen = 500;
    if (s < 160)      { b = 0; xb = s % 10; seg = s / 10; }
    else if (s < 368) { b = 1; s -= 160; xb = s % 13; seg = s / 13; }
    else              { b = 2; s -= 368; xb = s % 28; seg = s / 28; }
  }
  int Vb = vb_of(b), Mb = Vb + NSAMP;
  int Nout = d2 ? Mb : NGT;
  int Nin  = d2 ? NGT : Mb;
  int base_pt = xb * PTSPB;
  int tid = threadIdx.x;

  const float4* outPk = d2 ? g_pp[b] : g_gtp;
  const float4* inPk  = d2 ? g_gtp  : g_pp[b];

  ull xd[NPT], yd[NPT], zd[NPT]; float bs[NPT];
  #pragma unroll
  for (int k = 0; k < NPT; k++) {
    int j = base_pt + k * TILE + tid;
    float4 q = outPk[(j < Nout) ? j : 0];
    xd[k] = dup2(q.x); yd[k] = dup2(q.y); zd[k] = dup2(q.z);
    bs[k] = -3.4e38f;
  }

  int segLo = seg * segLen;
  int segHi = min(segLo + segLen, Nin);

  // ping-pong tiles: pair h holds points (2h, 2h+1) as {x0,x1,y0,y1}/{z0,z1,w0,w1}
  __shared__ float4 sxy[2][TILE2 / 2], szw[2][TILE2 / 2];

  const float4 pad = make_float4(0.f, 0.f, 0.f, -3.4e38f);
  {
    int j0 = segLo + 2 * tid, j1 = j0 + 1;
    float4 a = (j0 < segHi) ? inPk[j0] : pad;
    float4 c = (j1 < segHi) ? inPk[j1] : pad;
    sxy[0][tid] = make_float4(a.x, c.x, a.y, c.y);
    szw[0][tid] = make_float4(a.z, c.z, a.w, c.w);
  }
  __syncthreads();

  int p = 0;
  for (int tb = segLo; tb < segHi; tb += TILE2) {
    int nb = tb + TILE2;
    if (nb < segHi) {
      int j0 = nb + 2 * tid, j1 = j0 + 1;
      float4 a = (j0 < segHi) ? inPk[j0] : pad;
      float4 c = (j1 < segHi) ? inPk[j1] : pad;
      sxy[p ^ 1][tid] = make_float4(a.x, c.x, a.y, c.y);
      szw[p ^ 1][tid] = make_float4(a.z, c.z, a.w, c.w);
    }
    const ull* bx = (const ull*)&sxy[p][0];
    const ull* bz = (const ull*)&szw[p][0];
    #pragma unroll 8
    for (int t2 = 0; t2 < TILE2 / 2; t2++) {
      ull x01 = bx[2 * t2], y01 = bx[2 * t2 + 1];
      ull z01 = bz[2 * t2], w01 = bz[2 * t2 + 1];
      #pragma unroll
      for (int k = 0; k < NPT; k++) {
        ull s2 = ffma2(xd[k], x01, ffma2(yd[k], y01, ffma2(zd[k], z01, w01)));
        float lo, hi; unpk(s2, lo, hi);
        bs[k] = fmax3(bs[k], lo, hi);
      }
    }
    __syncthreads();
    p ^= 1;
  }

  #pragma unroll
  for (int k = 0; k < NPT; k++) {
    int j = base_pt + k * TILE + tid;
    if (j < Nout) {
      if (d2) g_d2seg[b][seg][j] = bs[k];
      else    atomicMax(&g_best1[b][j], enc_f(bs[k]));
    }
  }
}

// ---------------- post: rescan / combine / edge+normal (one node) ----------------
// [0,3362): rescan (warp/vertex; releases g_done)
// [3362,3599): chamfer combine (cham-dependent only)
// [3599,3915): edge+normal (spin-waits g_done == 3362; dispatched last -> safe)
#define POST_RESCAN_BLK 3362
#define POST_COMB_BLK   237
#define POST_EDGE_BLK   316
#define POST_BLKS (POST_RESCAN_BLK + POST_COMB_BLK + POST_EDGE_BLK)   // 3915
#define FIN_TARGET (POST_COMB_BLK + POST_EDGE_BLK)                    // 553
__global__ void k_post(Params P) {
  int blk = blockIdx.x;
  int tid = threadIdx.x;

  if (blk < POST_RESCAN_BLK) {           // ---- rescan: warp-per-vertex first-argmax
    int gw = blk * 4 + (tid >> 5);
    int lane = tid & 31;
    if (gw < VSUM) {
      int b, v; bv_of(gw, b, v);
      float best = -3.4e38f; int bseg = 0;
      #pragma unroll
      for (int s = 0; s < SEGS; s++) {
        float val = g_d2seg[b][s][v];
        if (val > best) { best = val; bseg = s; }
      }
      const int segLen = 500;
      int lo = bseg * segLen, hi = min(lo + segLen, NGT);
      float4 pv = g_pp[b][v];
      float x = pv.x, y = pv.y, z = pv.z;
      float bsv = -3.4e38f; int bi = 0x7fffffff;
      for (int j = lo + lane; j < hi; j += 32) {
        float4 q = __ldg(&g_gtp[j]);
        float s = score_of(x, y, z, q.x, q.y, q.z, q.w);
        if (s > bsv || (s == bsv && j < bi)) { bsv = s; bi = j; }
      }
      #pragma unroll
      for (int o = 16; o; o >>= 1) {
        float so = __shfl_down_sync(0xffffffffu, bsv, o);
        int   io = __shfl_down_sync(0xffffffffu, bi,  o);
        if (so > bsv || (so == bsv && io < bi)) { bsv = so; bi = io; }
      }
      if (lane == 0) g_imin[b][v] = bi;
    }
    __syncthreads();
    if (tid == 0) {
      __threadfence();                   // release: imin visible before count
      atomicAdd(&g_done, 1u);
    }
    return;
  }

  double v = 0.0;
  if (blk < POST_RESCAN_BLK + POST_COMB_BLK) {        // ---- chamfer combine
    int idx = (blk - POST_RESCAN_BLK) * TILE + tid;   // [0,30242)
    int b = -1, i = 0;
    if (idx < 8000)        { b = 0; i = idx; }
    else if (idx < 16000)  { b = 1; i = idx - 8000; }
    else if (idx < 30242)  { b = 2; i = idx - 16000; }
    if (b >= 0) {
      int Vb = vb_of(b), Mb = Vb + NSAMP;
      if (i < NGT) {
        float gg = -2.0f * g_gtp[i].w;
        float d = gg - 2.0f * dec_f(g_best1[b][i]);
        v += (3000.0 / NGT) * (double)d;
      }
      if (i < Mb) {
        float pp = -2.0f * g_pp[b][i].w;
        float m = -3.4e38f;
        #pragma unroll
        for (int s = 0; s < SEGS; s++) m = fmaxf(m, g_d2seg[b][s][i]);
        float d = pp - 2.0f * m;
        v += (3000.0 * 0.55 / Mb) * (double)d;
      }
    }
  } else {                                            // ---- edge + normal
    if (tid == 0) {
      while (*(volatile unsigned*)&g_done < (unsigned)POST_RESCAN_BLK) { }
      __threadfence();                   // acquire
    }
    __syncthreads();
    int idx = (blk - POST_RESCAN_BLK - POST_COMB_BLK) * TILE + tid;
    if (idx < ESUM) {
      int b, i;
      if (idx < 3 * V0)             { b = 0; i = idx; }
      else if (idx < 3 * (V0 + V1)) { b = 1; i = idx - 3 * V0; }
      else                          { b = 2; i = idx - 3 * (V0 + V1); }
      int E = 3 * vb_of(b);
      const int* eg = P.edges[b];
      int e0 = eg[2 * i], e1 = eg[2 * i + 1];
      float4 p0 = g_pp[b][e0], p1 = g_pp[b][e1];
      float dx = p0.x - p1.x, dy = p0.y - p1.y, dz = p0.z - p1.z;
      float esq = dx * dx + dy * dy + dz * dz;
      float inv = 1.0f / fmaxf(sqrtf(esq), 1e-12f);
      int gi = __ldcg(&g_imin[b][e0]);   // L1-bypass: written by other SMs this launch
      const float* nn = P.gtn + 3 * gi;
      float nx = nn[0], ny = nn[1], nz = nn[2];
      float ninv = 1.0f / fmaxf(sqrtf(nx * nx + ny * ny + nz * nz), 1e-12f);
      float dot = (dx * nx + dy * ny + dz * nz) * inv * ninv;
      v = (359.0 / E) * (double)esq + (0.5 / E) * (double)fabsf(dot);
    }
  }
  block_add(v);

  if (tid == 0) {                        // final-writer ticket + reset for next replay
    __threadfence();
    unsigned t = atomicAdd(&g_tick, 1u);
    if (t == (unsigned)(FIN_TARGET - 1)) {
      double total = atomicAdd(&g_loss, 0.0);
      P.out[0] = (float)total;
      __threadfence();
      g_loss = 0.0;
      g_tick = 0u;
      g_done = 0u;
    }
  }
}

// ---------------- launch ----------------
extern "C" void kernel_launch(void* const* d_in, const int* in_sizes, int n_in,
                              void* d_out, int out_size) {
  (void)in_sizes; (void)n_in; (void)out_size;
  Params p;
  p.gt  = (const float*)d_in[0];
  p.gtn = (const float*)d_in[1];
  for (int i = 0; i < 3; i++) {
    p.pred[i]  = (const float*)d_in[2 + 5 * i];
    p.bef[i]   = (const float*)d_in[3 + 5 * i];
    p.edges[i] = (const int*)  d_in[4 + 5 * i];
    p.faces[i] = (const int*)  d_in[5 + 5 * i];
    p.lap[i]   = (const int*)  d_in[6 + 5 * i];
  }
  p.out = (float*)d_out;

  dim3 bs(TILE);
  k_prep<<<PREP_BLKS, bs>>>(p);   // 557 blocks (+ laplacian loss)
  k_cham<<<1632,      bs>>>(p);   // double-buffered tiles, FMNMX3 accumulate
  k_post<<<POST_BLKS, bs>>>(p);   // rescan / combine / edge (ordered in-kernel)
}

// round 16
// speedup vs baseline: 1.6664x; 1.6664x over previous
#include <cuda_runtime.h>

#define NGT   8000
#define NSAMP 4000
#define TILE  128
#define TILE2 256             // inner tile (points) per sync
#define MAXV  10242
#define MAXM  (MAXV + NSAMP)
#define SEGS  16              // d2 segment count (fixed; rescan/combine depend on it)
#define NPT   4
#define PTSPB (TILE * NPT)    // 512 outer points per block
typedef unsigned long long ull;

static __device__ double g_loss;        // zero-init; final writer re-zeroes each run
static __device__ unsigned g_tick;      // same
static __device__ int    g_imin[3][MAXV];
static __device__ unsigned g_best1[3][NGT];          // encoded max-score, gt->pred
static __device__ float    g_d2seg[3][SEGS][MAXM];   // per-segment max score, pred->gt
static __device__ float4   g_gtp[NGT];               // gt packed (x,y,z,-0.5|q|^2)
static __device__ float4   g_pp[3][MAXM];            // pred+samples packed

#define V0 642
#define V1 2562
#define V2 10242
#define VSUM 13446
#define ESUM 40338

struct Params {
  const float* gt;  const float* gtn;
  const float* pred[3]; const float* bef[3];
  const int*   edges[3]; const int* faces[3]; const int* lap[3];
  float* out;
};

__device__ __forceinline__ int vb_of(int b) { return b == 0 ? V0 : (b == 1 ? V1 : V2); }

__device__ __forceinline__ unsigned enc_f(float f) {
  unsigned u = __float_as_uint(f);
  return (u & 0x80000000u) ? ~u : (u | 0x80000000u);
}
__device__ __forceinline__ float dec_f(unsigned u) {
  unsigned b = (u & 0x80000000u) ? (u ^ 0x80000000u) : ~u;
  return __uint_as_float(b);
}

// ---- packed f32x2 helpers ----
__device__ __forceinline__ ull ffma2(ull a, ull b, ull c) {
  ull d;
  asm("fma.rn.f32x2 %0, %1, %2, %3;" : "=l"(d) : "l"(a), "l"(b), "l"(c));
  return d;
}
__device__ __forceinline__ ull dup2(float v) {
  ull r; unsigned u = __float_as_uint(v);
  asm("mov.b64 %0, {%1, %1};" : "=l"(r) : "r"(u));
  return r;
}
__device__ __forceinline__ void unpk(ull v, float& lo, float& hi) {
  unsigned l, h;
  asm("mov.b64 {%0, %1}, %2;" : "=r"(l), "=r"(h) : "l"(v));
  lo = __uint_as_float(l); hi = __uint_as_float(h);
}
// 3-input max (PTX ISA 8.0+, sm_90+): SASS FMNMX3
__device__ __forceinline__ float fmax3(float a, float b, float c) {
  float d;
  asm("max.f32 %0, %1, %2, %3;" : "=f"(d) : "f"(a), "f"(b), "f"(c));
  return d;
}

// pinned-rounding score pieces (bit-identical everywhere)
__device__ __forceinline__ float wneg_of(float qx, float qy, float qz) {
  return -0.5f * __fmaf_rn(qx, qx, __fmaf_rn(qy, qy, __fmul_rn(qz, qz)));
}
__device__ __forceinline__ float score_of(float x, float y, float z,
                                          float qx, float qy, float qz, float w) {
  return __fmaf_rn(x, qx, __fmaf_rn(y, qy, __fmaf_rn(z, qz, w)));
}

// ---------------- threefry2x32 (exact JAX block) ----------------
__device__ __forceinline__ void tf(unsigned k0, unsigned k1,
                                   unsigned x0, unsigned x1,
                                   unsigned& o0, unsigned& o1) {
  unsigned ks2 = k0 ^ k1 ^ 0x1BD11BDAu;
  x0 += k0; x1 += k1;
#define R_(r) { x0 += x1; x1 = (x1 << (r)) | (x1 >> (32 - (r))); x1 ^= x0; }
  R_(13) R_(15) R_(26) R_(6)  x0 += k1;  x1 += ks2 + 1u;
  R_(17) R_(29) R_(16) R_(24) x0 += ks2; x1 += k0  + 2u;
  R_(13) R_(15) R_(26) R_(6)  x0 += k0;  x1 += k1  + 3u;
  R_(17) R_(29) R_(16) R_(24) x0 += k1;  x1 += ks2 + 4u;
  R_(13) R_(15) R_(26) R_(6)  x0 += ks2; x1 += k0  + 5u;
#undef R_
  o0 = x0; o1 = x1;
}

__device__ __forceinline__ void block_add(double v) {
  #pragma unroll
  for (int o = 16; o; o >>= 1) v += __shfl_down_sync(0xffffffffu, v, o);
  __shared__ double ws[4];
  int lane = threadIdx.x & 31, w = threadIdx.x >> 5;
  if (lane == 0) ws[w] = v;
  __syncthreads();
  if (w == 0) {
    double t = (lane < 4) ? ws[lane] : 0.0;
    t += __shfl_down_sync(0xffffffffu, t, 2);
    t += __shfl_down_sync(0xffffffffu, t, 1);
    if (lane == 0) atomicAdd(&g_loss, t);
  }
}

__device__ __forceinline__ void bv_of(int f, int& b, int& v) {
  if (f < V0)            { b = 0; v = f; }
  else if (f < V0 + V1)  { b = 1; v = f - V0; }
  else                   { b = 2; v = f - (V0 + V1); }
}

// ---------------- prep: block-aligned roles + laplacian loss ----------------
// [0,94) sample; [94,200) pack pred; [200,263) pack gt; [263,451) reset g_best1;
// [451,557) laplacian+move (calls block_add; roles are block-granular => uniform barrier)
#define PREP_BLKS 557
__global__ void k_prep(Params P) {
  int blk = blockIdx.x;
  int tid = threadIdx.x;

  if (blk < 94) {                        // ---- sampling (exact JAX PRNG)
    int i = blk * TILE + tid;
    if (i >= 12000) return;
    int b = i / NSAMP;
    int s_i = i - b * NSAMP;
    int Vb = vb_of(b);
    unsigned span = 2u * (unsigned)Vb;
    unsigned kb0, kb1; tf(0u, 42u, 0u, (unsigned)b, kb0, kb1);
    unsigned kf0, kf1, ku0, ku1, k10, k11, k20, k21, t0, t1, hi, lo, u0b, u1b;
    tf(kb0, kb1, 0u, 0u, kf0, kf1);
    tf(kb0, kb1, 0u, 1u, ku0, ku1);
    tf(kf0, kf1, 0u, 0u, k10, k11);
    tf(kf0, kf1, 0u, 1u, k20, k21);
    tf(k10, k11, 0u, (unsigned)s_i, t0, t1);            hi  = t0 ^ t1;
    tf(k20, k21, 0u, (unsigned)s_i, t0, t1);            lo  = t0 ^ t1;
    tf(ku0, ku1, 0u, (unsigned)(2 * s_i),     t0, t1);  u0b = t0 ^ t1;
    tf(ku0, ku1, 0u, (unsigned)(2 * s_i + 1), t0, t1);  u1b = t0 ^ t1;
    unsigned m = 65536u % span; m = (m * m) % span;
    int fidx = (int)(((hi % span) * m + (lo % span)) % span);
    float u0 = __uint_as_float((u0b >> 9) | 0x3F800000u) - 1.0f;
    float u1 = __uint_as_float((u1b >> 9) | 0x3F800000u) - 1.0f;
    float r1 = sqrtf(u0);
    float w0 = 1.0f - r1, w1 = r1 * (1.0f - u1), w2 = r1 * u1;
    const int* f = P.faces[b] + 3 * fidx;
    const float* pr = P.pred[b];
    int v0 = f[0], v1 = f[1], v2 = f[2];
    float sx = w0 * pr[3 * v0]     + w1 * pr[3 * v1]     + w2 * pr[3 * v2];
    float sy = w0 * pr[3 * v0 + 1] + w1 * pr[3 * v1 + 1] + w2 * pr[3 * v2 + 1];
    float sz = w0 * pr[3 * v0 + 2] + w1 * pr[3 * v1 + 2] + w2 * pr[3 * v2 + 2];
    g_pp[b][Vb + s_i] = make_float4(sx, sy, sz, wneg_of(sx, sy, sz));
    return;
  } else if (blk < 200) {                // ---- pack pred vertices
    int i = (blk - 94) * TILE + tid;
    if (i < VSUM) {
      int b, v; bv_of(i, b, v);
      const float* s = P.pred[b] + 3 * v;
      float x = s[0], y = s[1], z = s[2];
      g_pp[b][v] = make_float4(x, y, z, wneg_of(x, y, z));
    }
    return;
  } else if (blk < 263) {                // ---- pack gt
    int g = (blk - 200) * TILE + tid;
    if (g < NGT) {
      const float* s = P.gt + 3 * g;
      float x = s[0], y = s[1], z = s[2];
      g_gtp[g] = make_float4(x, y, z, wneg_of(x, y, z));
    }
    return;
  } else if (blk < 451) {                // ---- reset g_best1
    int j = (blk - 263) * TILE + tid;
    if (j < 3 * NGT) (&g_best1[0][0])[j] = 0u;
    return;
  }

  // ---- laplacian + move loss (blocks [451,557); ALL threads reach block_add)
  double acc = 0.0;
  {
    int idx = (blk - 451) * TILE + tid;
    if (idx < VSUM) {
      int b, i; bv_of(idx, b, i);
      int Vb = vb_of(b);
      float lapc = (b == 0) ? 0.2f : 1.0f;
      const int* row = P.lap[b] + 10 * i;
      float cnt = (float)row[9];
      const float* pr = P.pred[b];
      const float* bf = P.bef[b];
      float spx = 0, spy = 0, spz = 0, sbx = 0, sby = 0, sbz = 0;
      #pragma unroll
      for (int k = 0; k < 8; k++) {
        int n = row[k];
        if (n >= 0) {
          spx += pr[3 * n]; spy += pr[3 * n + 1]; spz += pr[3 * n + 2];
          sbx += bf[3 * n]; sby += bf[3 * n + 1]; sbz += bf[3 * n + 2];
        }
      }
      float lbx = bf[3 * i]     - sbx / cnt;
      float lby = bf[3 * i + 1] - sby / cnt;
      float lbz = bf[3 * i + 2] - sbz / cnt;
      float lpx = pr[3 * i]     - spx / cnt;
      float lpy = pr[3 * i + 1] - spy / cnt;
      float lpz = pr[3 * i + 2] - spz / cnt;
      float d0 = lbx - lpx, d1 = lby - lpy, d2 = lbz - lpz;
      float lapsq = d0 * d0 + d1 * d1 + d2 * d2;
      float m0 = bf[3 * i] - pr[3 * i];
      float m1 = bf[3 * i + 1] - pr[3 * i + 1];
      float m2 = bf[3 * i + 2] - pr[3 * i + 2];
      float movesq = m0 * m0 + m1 * m1 + m2 * m2;
      acc = (1500.0 * (double)lapc / Vb) * (double)lapsq;
      if (b > 0) acc += (50.0 * (double)lapc / Vb) * (double)movesq;
    }
  }
  block_add(acc);
}

// ---------------- fused chamfer: double-buffered 256-pt tiles + FMNMX3 ----------------
// d1 (inner = Mb): b0 10 segs (len 465), b1 13 (505), b2 28 (509); 16 xb -> 816 blocks
// d2 (inner = NGT): SEGS=16 (len 500); xb 10/13/28 -> 816.  Total 1632.
__global__ void __launch_bounds__(TILE, 8) k_cham(Params P) {
  int s = blockIdx.x;
  int b, xb, seg, segLen; bool d2;
  if (s < 816) {
    d2 = false;
    if (s < 160)      { b = 0; segLen = 465; }
    else if (s < 368) { b = 1; s -= 160; segLen = 505; }
    else              { b = 2; s -= 368; segLen = 509; }
    xb = s & 15; seg = s >> 4;
  } else {
    d2 = true; s -= 816; segLen = 500;
    if (s < 160)      { b = 0; xb = s % 10; seg = s / 10; }
    else if (s < 368) { b = 1; s -= 160; xb = s % 13; seg = s / 13; }
    else              { b = 2; s -= 368; xb = s % 28; seg = s / 28; }
  }
  int Vb = vb_of(b), Mb = Vb + NSAMP;
  int Nout = d2 ? Mb : NGT;
  int Nin  = d2 ? NGT : Mb;
  int base_pt = xb * PTSPB;
  int tid = threadIdx.x;

  const float4* outPk = d2 ? g_pp[b] : g_gtp;
  const float4* inPk  = d2 ? g_gtp  : g_pp[b];

  ull xd[NPT], yd[NPT], zd[NPT]; float bs[NPT];
  #pragma unroll
  for (int k = 0; k < NPT; k++) {
    int j = base_pt + k * TILE + tid;
    float4 q = outPk[(j < Nout) ? j : 0];
    xd[k] = dup2(q.x); yd[k] = dup2(q.y); zd[k] = dup2(q.z);
    bs[k] = -3.4e38f;
  }

  int segLo = seg * segLen;
  int segHi = min(segLo + segLen, Nin);

  // ping-pong tiles: pair h holds points (2h, 2h+1) as {x0,x1,y0,y1}/{z0,z1,w0,w1}
  __shared__ float4 sxy[2][TILE2 / 2], szw[2][TILE2 / 2];

  const float4 pad = make_float4(0.f, 0.f, 0.f, -3.4e38f);
  {
    int j0 = segLo + 2 * tid, j1 = j0 + 1;
    float4 a = (j0 < segHi) ? inPk[j0] : pad;
    float4 c = (j1 < segHi) ? inPk[j1] : pad;
    sxy[0][tid] = make_float4(a.x, c.x, a.y, c.y);
    szw[0][tid] = make_float4(a.z, c.z, a.w, c.w);
  }
  __syncthreads();

  int p = 0;
  for (int tb = segLo; tb < segHi; tb += TILE2) {
    int nb = tb + TILE2;
    if (nb < segHi) {
      int j0 = nb + 2 * tid, j1 = j0 + 1;
      float4 a = (j0 < segHi) ? inPk[j0] : pad;
      float4 c = (j1 < segHi) ? inPk[j1] : pad;
      sxy[p ^ 1][tid] = make_float4(a.x, c.x, a.y, c.y);
      szw[p ^ 1][tid] = make_float4(a.z, c.z, a.w, c.w);
    }
    const ull* bx = (const ull*)&sxy[p][0];
    const ull* bz = (const ull*)&szw[p][0];
    #pragma unroll 8
    for (int t2 = 0; t2 < TILE2 / 2; t2++) {
      ull x01 = bx[2 * t2], y01 = bx[2 * t2 + 1];
      ull z01 = bz[2 * t2], w01 = bz[2 * t2 + 1];
      #pragma unroll
      for (int k = 0; k < NPT; k++) {
        ull s2 = ffma2(xd[k], x01, ffma2(yd[k], y01, ffma2(zd[k], z01, w01)));
        float lo, hi; unpk(s2, lo, hi);
        bs[k] = fmax3(bs[k], lo, hi);
      }
    }
    __syncthreads();
    p ^= 1;
  }

  #pragma unroll
  for (int k = 0; k < NPT; k++) {
    int j = base_pt + k * TILE + tid;
    if (j < Nout) {
      if (d2) g_d2seg[b][seg][j] = bs[k];
      else    atomicMax(&g_best1[b][j], enc_f(bs[k]));
    }
  }
}

// ---------------- mid: rescan + chamfer-combine (both depend only on cham) ----------------
// [0,3362): rescan (warp/vertex); [3362,3599): combine
#define MID_RESCAN_BLK 3362
#define MID_COMB_BLK   237
#define MID_BLKS (MID_RESCAN_BLK + MID_COMB_BLK)   // 3599
__global__ void k_mid(Params P) {
  int blk = blockIdx.x;
  int tid = threadIdx.x;

  if (blk < MID_RESCAN_BLK) {            // ---- rescan: warp-per-vertex first-argmax
    int gw = blk * 4 + (tid >> 5);
    int lane = tid & 31;
    if (gw >= VSUM) return;
    int b, v; bv_of(gw, b, v);
    float best = -3.4e38f; int bseg = 0;
    #pragma unroll
    for (int s = 0; s < SEGS; s++) {
      float val = g_d2seg[b][s][v];
      if (val > best) { best = val; bseg = s; }
    }
    const int segLen = 500;
    int lo = bseg * segLen, hi = min(lo + segLen, NGT);
    float4 pv = g_pp[b][v];
    float x = pv.x, y = pv.y, z = pv.z;
    float bsv = -3.4e38f; int bi = 0x7fffffff;
    for (int j = lo + lane; j < hi; j += 32) {
      float4 q = __ldg(&g_gtp[j]);
      float s = score_of(x, y, z, q.x, q.y, q.z, q.w);
      if (s > bsv || (s == bsv && j < bi)) { bsv = s; bi = j; }
    }
    #pragma unroll
    for (int o = 16; o; o >>= 1) {
      float so = __shfl_down_sync(0xffffffffu, bsv, o);
      int   io = __shfl_down_sync(0xffffffffu, bi,  o);
      if (so > bsv || (so == bsv && io < bi)) { bsv = so; bi = io; }
    }
    if (lane == 0) g_imin[b][v] = bi;
    return;
  }

  // ---- chamfer combine (blocks [3362,3599); ALL threads reach block_add)
  double v = 0.0;
  {
    int idx = (blk - MID_RESCAN_BLK) * TILE + tid;   // [0,30242)
    int b = -1, i = 0;
    if (idx < 8000)        { b = 0; i = idx; }
    else if (idx < 16000)  { b = 1; i = idx - 8000; }
    else if (idx < 30242)  { b = 2; i = idx - 16000; }
    if (b >= 0) {
      int Vb = vb_of(b), Mb = Vb + NSAMP;
      if (i < NGT) {
        float gg = -2.0f * g_gtp[i].w;
        float d = gg - 2.0f * dec_f(g_best1[b][i]);
        v += (3000.0 / NGT) * (double)d;
      }
      if (i < Mb) {
        float pp = -2.0f * g_pp[b][i].w;
        float m = -3.4e38f;
        #pragma unroll
        for (int s = 0; s < SEGS; s++) m = fmaxf(m, g_d2seg[b][s][i]);
        float d = pp - 2.0f * m;
        v += (3000.0 * 0.55 / Mb) * (double)d;
      }
    }
  }
  block_add(v);
}

// ---------------- edge + normal + final write (after mid via graph edge) ----------------
#define EDGE_BLKS 316
__global__ void k_edgefin(Params P) {
  int idx = blockIdx.x * TILE + threadIdx.x;
  double v = 0.0;
  if (idx < ESUM) {
    int b, i;
    if (idx < 3 * V0)             { b = 0; i = idx; }
    else if (idx < 3 * (V0 + V1)) { b = 1; i = idx - 3 * V0; }
    else                          { b = 2; i = idx - 3 * (V0 + V1); }
    int E = 3 * vb_of(b);
    const int* eg = P.edges[b];
    int e0 = eg[2 * i], e1 = eg[2 * i + 1];
    float4 p0 = g_pp[b][e0], p1 = g_pp[b][e1];
    float dx = p0.x - p1.x, dy = p0.y - p1.y, dz = p0.z - p1.z;
    float esq = dx * dx + dy * dy + dz * dz;
    float inv = 1.0f / fmaxf(sqrtf(esq), 1e-12f);
    int gi = g_imin[b][e0];
    const float* nn = P.gtn + 3 * gi;
    float nx = nn[0], ny = nn[1], nz = nn[2];
    float ninv = 1.0f / fmaxf(sqrtf(nx * nx + ny * ny + nz * nz), 1e-12f);
    float dot = (dx * nx + dy * ny + dz * nz) * inv * ninv;
    v = (359.0 / E) * (double)esq + (0.5 / E) * (double)fabsf(dot);
  }
  block_add(v);

  if (threadIdx.x == 0) {                // final-writer ticket + reset for next replay
    __threadfence();
    unsigned t = atomicAdd(&g_tick, 1u);
    if (t == (unsigned)(EDGE_BLKS - 1)) {
      double total = atomicAdd(&g_loss, 0.0);
      P.out[0] = (float)total;
      __threadfence();
      g_loss = 0.0;
      g_tick = 0u;
    }
  }
}

// ---------------- launch ----------------
extern "C" void kernel_launch(void* const* d_in, const int* in_sizes, int n_in,
                              void* d_out, int out_size) {
  (void)in_sizes; (void)n_in; (void)out_size;
  Params p;
  p.gt  = (const float*)d_in[0];
  p.gtn = (const float*)d_in[1];
  for (int i = 0; i < 3; i++) {
    p.pred[i]  = (const float*)d_in[2 + 5 * i];
    p.bef[i]   = (const float*)d_in[3 + 5 * i];
    p.edges[i] = (const int*)  d_in[4 + 5 * i];
    p.faces[i] = (const int*)  d_in[5 + 5 * i];
    p.lap[i]   = (const int*)  d_in[6 + 5 * i];
  }
  p.out = (float*)d_out;

  dim3 bs(TILE);
  k_prep   <<<PREP_BLKS, bs>>>(p);   // 557 blocks (+ laplacian loss)
  k_cham   <<<1632,      bs>>>(p);   // double-buffered tiles, FMNMX3 accumulate
  k_mid    <<<MID_BLKS,  bs>>>(p);   // rescan + combine (parallel, no intra-ordering)
  k_edgefin<<<EDGE_BLKS, bs>>>(p);   // edge+normal + final ticket/reset
}